// round 12
// baseline (speedup 1.0000x reference)
#include <cuda_runtime.h>

#define BB 8
#define SS 4096
#define HH 2048
#define EE 8
#define CAP 512
#define NTOK (BB*SS)      /* 32768 */
#define DD (NTOK*EE)      /* 262144 */

typedef unsigned long long u64;

// per-block partial sums for aux/z losses: [512 blocks][2]
__device__ float g_part[1024];

__device__ __forceinline__ void ffma2(u64 &acc, u64 a, u64 b) {
    asm("fma.rn.f32x2 %0, %1, %2, %0;" : "+l"(acc) : "l"(a), "l"(b));
}
__device__ __forceinline__ u64 packf2(float a, float b) {
    return (u64)__float_as_uint(a) | ((u64)__float_as_uint(b) << 32);
}
__device__ __forceinline__ float f_lo(u64 v) { return __uint_as_float((unsigned)v); }
__device__ __forceinline__ float f_hi(u64 v) { return __uint_as_float((unsigned)(v >> 32)); }

__device__ __forceinline__ void token_epilogue(const float* lg, float* __restrict__ probs_out,
                                               long tok, float& aux, float& zz) {
    float m = lg[0];
#pragma unroll
    for (int e = 1; e < 8; e++) m = fmaxf(m, lg[e]);
    float p[8];
    float s = 0.f;
#pragma unroll
    for (int e = 0; e < 8; e++) { p[e] = __expf(lg[e] - m); s += p[e]; }
    float inv = 1.f / s;
    float psq = 0.f;
#pragma unroll
    for (int e = 0; e < 8; e++) { p[e] *= inv; psq += p[e] * p[e]; }
    float4* o = (float4*)(probs_out + (size_t)tok * 8);
    o[0] = make_float4(p[0], p[1], p[2], p[3]);
    o[1] = make_float4(p[4], p[5], p[6], p[7]);
    float lse = m + __logf(s);
    aux += psq;
    zz += lse * lse;
}

// ---------------------------------------------------------------------------
// Kernel 1: logits GEMM (f32x2-packed) + softmax + probs + loss partials
// grid 512, block 256. Each block: 64 tokens. Thread: 2 tokens x 256 K-values.
// ---------------------------------------------------------------------------
__global__ __launch_bounds__(256) void router_kernel(const float* __restrict__ hid,
                                                     const float* __restrict__ W,
                                                     float* __restrict__ probs_out) {
    extern __shared__ ulonglong2 swp[];  // [e*512 + q] : 4 floats W[4q..4q+3][e] as 2 f32x2; 64KB

    int tid = threadIdx.x;

    // Build paired-W shared layout
    for (int idx = tid; idx < 4096; idx += 256) {
        int e = idx >> 9;
        int q = idx & 511;
        int h = q * 4;
        float w0 = W[(h + 0) * 8 + e];
        float w1 = W[(h + 1) * 8 + e];
        float w2 = W[(h + 2) * 8 + e];
        float w3 = W[(h + 3) * 8 + e];
        ulonglong2 v;
        v.x = packf2(w0, w1);
        v.y = packf2(w2, w3);
        swp[idx] = v;
    }
    __syncthreads();

    int kseg = tid & 7;        // which 256-wide K segment (interleaved: h = 4*kseg + 32*i)
    int pair = tid >> 3;       // token pair within block (0..31)
    long tok0 = (long)blockIdx.x * 64 + pair * 2;

    const ulonglong2* p0 = (const ulonglong2*)(hid + (size_t)tok0 * HH + 4 * kseg);
    const ulonglong2* p1 = p0 + (HH / 4);   // next token (+2048 floats = +512 ulonglong2)

    u64 acc0[8] = {0, 0, 0, 0, 0, 0, 0, 0};
    u64 acc1[8] = {0, 0, 0, 0, 0, 0, 0, 0};

#pragma unroll 2
    for (int i = 0; i < 64; i++) {
        ulonglong2 a = p0[i * 8];
        ulonglong2 b = p1[i * 8];
#pragma unroll
        for (int e = 0; e < 8; e++) {
            ulonglong2 w = swp[e * 512 + kseg + 8 * i];
            ffma2(acc0[e], a.x, w.x);
            ffma2(acc0[e], a.y, w.y);
            ffma2(acc1[e], b.x, w.x);
            ffma2(acc1[e], b.y, w.y);
        }
    }

    float lg0[8], lg1[8];
#pragma unroll
    for (int e = 0; e < 8; e++) {
        lg0[e] = f_lo(acc0[e]) + f_hi(acc0[e]);
        lg1[e] = f_lo(acc1[e]) + f_hi(acc1[e]);
    }

    // reduce across the 8 K-segment lanes (lanes l..l+7 share a token pair)
#pragma unroll
    for (int off = 4; off; off >>= 1) {
#pragma unroll
        for (int e = 0; e < 8; e++) {
            lg0[e] += __shfl_down_sync(0xffffffffu, lg0[e], off, 8);
            lg1[e] += __shfl_down_sync(0xffffffffu, lg1[e], off, 8);
        }
    }

    float auxAcc = 0.f, zAcc = 0.f;
    if (kseg == 0) {
        token_epilogue(lg0, probs_out, tok0, auxAcc, zAcc);
        token_epilogue(lg1, probs_out, tok0 + 1, auxAcc, zAcc);
    }

    // deterministic block reduction of loss partials
#pragma unroll
    for (int off = 16; off; off >>= 1) {
        auxAcc += __shfl_down_sync(0xffffffffu, auxAcc, off);
        zAcc += __shfl_down_sync(0xffffffffu, zAcc, off);
    }
    __shared__ float sA[8], sB[8];
    if ((tid & 31) == 0) { sA[tid >> 5] = auxAcc; sB[tid >> 5] = zAcc; }
    __syncthreads();
    if (tid == 0) {
        float a = 0.f, z = 0.f;
#pragma unroll
        for (int w = 0; w < 8; w++) { a += sA[w]; z += sB[w]; }
        g_part[blockIdx.x * 2 + 0] = a;
        g_part[blockIdx.x * 2 + 1] = z;
    }
}

// ---------------------------------------------------------------------------
// Kernel 2: per-batch-row capacity scan -> dispatch & combine tensors
// grid 8 (one per batch row), block 512. Thread t owns tokens t*8..t*8+7.
// ---------------------------------------------------------------------------
__global__ __launch_bounds__(512) void dispatch_kernel(const float* __restrict__ probs,
                                                       float* __restrict__ dispatch,
                                                       float* __restrict__ combine) {
    __shared__ int sc[8 * 512];  // [e][t]
    int b = blockIdx.x;
    int t = threadIdx.x;
    const float4* pr = (const float4*)(probs + (size_t)b * SS * 8);
    int base = t * 8;

    int myi[8];
    float myw[8];
    int cnt[8] = {0, 0, 0, 0, 0, 0, 0, 0};
#pragma unroll
    for (int j = 0; j < 8; j++) {
        float4 lo = pr[(base + j) * 2];
        float4 hi = pr[(base + j) * 2 + 1];
        float v[8] = {lo.x, lo.y, lo.z, lo.w, hi.x, hi.y, hi.z, hi.w};
        float m = v[0];
        int mi = 0;
#pragma unroll
        for (int e = 1; e < 8; e++)
            if (v[e] > m) { m = v[e]; mi = e; }
        myi[j] = mi;
        myw[j] = m;
        cnt[mi]++;
    }

#pragma unroll
    for (int e = 0; e < 8; e++) sc[e * 512 + t] = cnt[e];
    __syncthreads();

    // Hillis-Steele inclusive scan over 512 threads, 8 counters each
    for (int off = 1; off < 512; off <<= 1) {
        int v[8];
#pragma unroll
        for (int e = 0; e < 8; e++)
            v[e] = sc[e * 512 + t] + (t >= off ? sc[e * 512 + t - off] : 0);
        __syncthreads();
#pragma unroll
        for (int e = 0; e < 8; e++) sc[e * 512 + t] = v[e];
        __syncthreads();
    }

    int run[8];
#pragma unroll
    for (int e = 0; e < 8; e++) run[e] = sc[e * 512 + t] - cnt[e];  // exclusive prefix

    float4* dO = (float4*)(dispatch + (size_t)b * SS * 8);
    float4* cO = (float4*)(combine + (size_t)b * SS * 8);
#pragma unroll
    for (int j = 0; j < 8; j++) {
        int e = myi[j];
        int pos = run[e]++;
        float keep = (pos < CAP) ? 1.f : 0.f;
        float cw = keep * myw[j];
        float4 d0 = make_float4(e == 0 ? keep : 0.f, e == 1 ? keep : 0.f,
                                e == 2 ? keep : 0.f, e == 3 ? keep : 0.f);
        float4 d1 = make_float4(e == 4 ? keep : 0.f, e == 5 ? keep : 0.f,
                                e == 6 ? keep : 0.f, e == 7 ? keep : 0.f);
        float4 c0 = make_float4(e == 0 ? cw : 0.f, e == 1 ? cw : 0.f,
                                e == 2 ? cw : 0.f, e == 3 ? cw : 0.f);
        float4 c1 = make_float4(e == 4 ? cw : 0.f, e == 5 ? cw : 0.f,
                                e == 6 ? cw : 0.f, e == 7 ? cw : 0.f);
        dO[(base + j) * 2] = d0;
        dO[(base + j) * 2 + 1] = d1;
        cO[(base + j) * 2] = c0;
        cO[(base + j) * 2 + 1] = c1;
    }
}

// ---------------------------------------------------------------------------
// Kernel 3: deterministic final reduction of loss partials
// ---------------------------------------------------------------------------
__global__ __launch_bounds__(256) void loss_kernel(float* __restrict__ out) {
    __shared__ float rA[256], rB[256];
    int t = threadIdx.x;
    rA[t] = g_part[t * 2] + g_part[(t + 256) * 2];
    rB[t] = g_part[t * 2 + 1] + g_part[(t + 256) * 2 + 1];
    __syncthreads();
    for (int off = 128; off; off >>= 1) {
        if (t < off) { rA[t] += rA[t + off]; rB[t] += rB[t + off]; }
        __syncthreads();
    }
    if (t == 0) {
        out[3 * (size_t)DD + 0] = rA[0] * ((float)EE / (float)NTOK);  // aux_loss
        out[3 * (size_t)DD + 1] = rB[0] / (float)NTOK;                // z_loss
    }
}

extern "C" void kernel_launch(void* const* d_in, const int* in_sizes, int n_in,
                              void* d_out, int out_size) {
    (void)in_sizes; (void)n_in; (void)out_size;
    const float* hid = (const float*)d_in[0];
    const float* W = (const float*)d_in[1];
    float* out = (float*)d_out;

    float* dispatch = out;
    float* combine = out + (size_t)DD;
    float* probs = out + 2 * (size_t)DD;

    cudaFuncSetAttribute(router_kernel, cudaFuncAttributeMaxDynamicSharedMemorySize, 65536);

    router_kernel<<<512, 256, 65536>>>(hid, W, probs);
    dispatch_kernel<<<8, 512>>>(probs, dispatch, combine);
    loss_kernel<<<1, 256>>>(out);
}

// round 13
// speedup vs baseline: 1.9850x; 1.9850x over previous
#include <cuda_runtime.h>

#define SS 4096
#define HH 2048
#define EE 8
#define CAP 512
#define NTOK 32768
#define DD (NTOK*EE)          /* 262144 */
#define NBLK 444              /* 148 SMs x 3 CTAs -> exactly 1 wave */
#define NPAIR_TOT 16384

typedef unsigned long long u64;

// per-block loss partials; zero-initialized .bss, blocks >= NBLK never write
__device__ float g_part[1024];

__device__ __forceinline__ void ffma2(u64 &acc, u64 a, u64 b) {
    asm("fma.rn.f32x2 %0, %1, %2, %0;" : "+l"(acc) : "l"(a), "l"(b));
}
__device__ __forceinline__ u64 packf2(float a, float b) {
    return (u64)__float_as_uint(a) | ((u64)__float_as_uint(b) << 32);
}
__device__ __forceinline__ float f_lo(u64 v) { return __uint_as_float((unsigned)v); }
__device__ __forceinline__ float f_hi(u64 v) { return __uint_as_float((unsigned)(v >> 32)); }

__device__ __forceinline__ void token_epilogue(const float* lg, float* __restrict__ probs_out,
                                               long tok, float& aux, float& zz) {
    float m = lg[0];
#pragma unroll
    for (int e = 1; e < 8; e++) m = fmaxf(m, lg[e]);
    float p[8];
    float s = 0.f;
#pragma unroll
    for (int e = 0; e < 8; e++) { p[e] = __expf(lg[e] - m); s += p[e]; }
    float inv = 1.f / s;
    float psq = 0.f;
#pragma unroll
    for (int e = 0; e < 8; e++) { p[e] *= inv; psq += p[e] * p[e]; }
    float4* o = (float4*)(probs_out + (size_t)tok * 8);
    o[0] = make_float4(p[0], p[1], p[2], p[3]);
    o[1] = make_float4(p[4], p[5], p[6], p[7]);
    float lse = m + __logf(s);
    aux += psq;
    zz += lse * lse;
}

// ---------------------------------------------------------------------------
// Kernel 1: logits GEMM + softmax + probs + loss partials.
// grid 444, block 256, 64KB dyn smem (W paired layout). Balanced pair ranges.
// Distance-2 software prefetch pipeline on the hidden-state stream.
// ---------------------------------------------------------------------------
__global__ __launch_bounds__(256, 3) void router_kernel(const float* __restrict__ hid,
                                                        const float* __restrict__ W,
                                                        float* __restrict__ probs_out) {
    extern __shared__ ulonglong2 swp[];  // [e*512 + q]: W[4q..4q+3][e] as 2 f32x2

    int tid = threadIdx.x;
    for (int idx = tid; idx < 4096; idx += 256) {
        int e = idx >> 9;
        int q = idx & 511;
        int h = q * 4;
        ulonglong2 v;
        v.x = packf2(W[(h + 0) * 8 + e], W[(h + 1) * 8 + e]);
        v.y = packf2(W[(h + 2) * 8 + e], W[(h + 3) * 8 + e]);
        swp[idx] = v;
    }
    __syncthreads();

    int kseg = tid & 7;
    int slot = tid >> 3;   // 0..31
    int wid  = tid >> 5;   // 0..7
    int r0 = (int)(((long)blockIdx.x * NPAIR_TOT) / NBLK);
    int r1 = (int)(((long)(blockIdx.x + 1) * NPAIR_TOT) / NBLK);
    int npairs = r1 - r0;  // 36 or 37

    float auxAcc = 0.f, zAcc = 0.f;

    for (int base = 0; base < npairs; base += 32) {
        if (base + (wid << 2) >= npairs) continue;   // whole warp idle this round
        int rel = base + slot;
        bool active = rel < npairs;
        int pr = r0 + (active ? rel : (npairs - 1)); // clamp keeps warp converged
        long tok0 = (long)pr * 2;

        const ulonglong2* p0 = (const ulonglong2*)(hid + (size_t)tok0 * HH + 4 * kseg);
        const ulonglong2* p1 = p0 + (HH / 4);

        u64 acc0[8] = {0,0,0,0,0,0,0,0};
        u64 acc1[8] = {0,0,0,0,0,0,0,0};

        // pipeline prologue: 2 iterations in flight
        ulonglong2 A0 = p0[0],  B0 = p1[0];
        ulonglong2 A1 = p0[8],  B1 = p1[8];

        for (int i = 0; i < 62; i++) {
            ulonglong2 A2 = p0[(i + 2) * 8];     // prefetch i+2 BEFORE consuming i
            ulonglong2 B2 = p1[(i + 2) * 8];
            const ulonglong2* ws = &swp[kseg + 8 * i];
#pragma unroll
            for (int e = 0; e < 8; e++) {
                ulonglong2 w = ws[e * 512];
                ffma2(acc0[e], A0.x, w.x);
                ffma2(acc0[e], A0.y, w.y);
                ffma2(acc1[e], B0.x, w.x);
                ffma2(acc1[e], B0.y, w.y);
            }
            A0 = A1; B0 = B1; A1 = A2; B1 = B2;
        }
        // peeled tail i = 62, 63
#pragma unroll
        for (int t2 = 0; t2 < 2; t2++) {
            const ulonglong2* ws = &swp[kseg + 8 * (62 + t2)];
#pragma unroll
            for (int e = 0; e < 8; e++) {
                ulonglong2 w = ws[e * 512];
                ffma2(acc0[e], A0.x, w.x);
                ffma2(acc0[e], A0.y, w.y);
                ffma2(acc1[e], B0.x, w.x);
                ffma2(acc1[e], B0.y, w.y);
            }
            A0 = A1; B0 = B1;
        }

        float lg0[8], lg1[8];
#pragma unroll
        for (int e = 0; e < 8; e++) {
            lg0[e] = f_lo(acc0[e]) + f_hi(acc0[e]);
            lg1[e] = f_lo(acc1[e]) + f_hi(acc1[e]);
        }
#pragma unroll
        for (int off = 4; off; off >>= 1) {
#pragma unroll
            for (int e = 0; e < 8; e++) {
                lg0[e] += __shfl_down_sync(0xffffffffu, lg0[e], off, 8);
                lg1[e] += __shfl_down_sync(0xffffffffu, lg1[e], off, 8);
            }
        }
        if (kseg == 0 && active) {
            token_epilogue(lg0, probs_out, tok0, auxAcc, zAcc);
            token_epilogue(lg1, probs_out, tok0 + 1, auxAcc, zAcc);
        }
    }

    // deterministic block reduction of loss partials
#pragma unroll
    for (int off = 16; off; off >>= 1) {
        auxAcc += __shfl_down_sync(0xffffffffu, auxAcc, off);
        zAcc   += __shfl_down_sync(0xffffffffu, zAcc, off);
    }
    __shared__ float sA[8], sB[8];
    if ((tid & 31) == 0) { sA[wid] = auxAcc; sB[wid] = zAcc; }
    __syncthreads();
    if (tid == 0) {
        float a = 0.f, z = 0.f;
#pragma unroll
        for (int w = 0; w < 8; w++) { a += sA[w]; z += sB[w]; }
        g_part[blockIdx.x * 2 + 0] = a;
        g_part[blockIdx.x * 2 + 1] = z;
    }
}

// ---------------------------------------------------------------------------
// Kernel 2: capacity scan. grid 8, block 512.
// Coalesced argmax pass -> smem; packed 16-bit counters; shfl scan; coalesced
// staged writes.
// ---------------------------------------------------------------------------
__global__ __launch_bounds__(512) void dispatch_kernel(const float* __restrict__ probs,
                                                       float* __restrict__ dispatch,
                                                       float* __restrict__ combine) {
    __shared__ unsigned char s_eid[4096];   // expert id (bit7 = keep after phase 3)
    __shared__ float s_w[4096];             // weight, then combine weight
    __shared__ u64 s_ws[32];                // warp scan totals [pack0:0..15][pack1:16..31]

    int b = blockIdx.x;
    int t = threadIdx.x;
    int lane = t & 31;
    int w = t >> 5;  // 0..15
    const float4* pr = (const float4*)(probs + (size_t)b * SS * 8);

    // Phase 1: coalesced argmax (lanes read consecutive tokens)
#pragma unroll
    for (int k = 0; k < 8; k++) {
        int tok = k * 512 + t;
        float4 lo = pr[tok * 2];
        float4 hi = pr[tok * 2 + 1];
        float v[8] = {lo.x, lo.y, lo.z, lo.w, hi.x, hi.y, hi.z, hi.w};
        float m = v[0];
        int mi = 0;
#pragma unroll
        for (int e = 1; e < 8; e++)
            if (v[e] > m) { m = v[e]; mi = e; }
        s_eid[tok] = (unsigned char)mi;
        s_w[tok] = m;
    }
    __syncthreads();

    // Phase 2: per-thread counts of contiguous tokens t*8..t*8+7, packed 4x16b
    int base = t * 8;
    unsigned char eid[8];
    u64 c0 = 0, c1 = 0;
#pragma unroll
    for (int j = 0; j < 8; j++) {
        int e = s_eid[base + j];
        eid[j] = (unsigned char)e;
        u64 inc = 1ULL << ((e & 3) * 16);
        if (e < 4) c0 += inc; else c1 += inc;
    }
    // warp inclusive scan
    u64 i0 = c0, i1 = c1;
#pragma unroll
    for (int off = 1; off < 32; off <<= 1) {
        u64 n0 = __shfl_up_sync(0xffffffffu, i0, off);
        u64 n1 = __shfl_up_sync(0xffffffffu, i1, off);
        if (lane >= off) { i0 += n0; i1 += n1; }
    }
    if (lane == 31) { s_ws[w] = i0; s_ws[16 + w] = i1; }
    __syncthreads();
    if (t == 0) {   // exclusive scan of 16 warp totals (trivial)
        u64 a0 = 0, a1 = 0;
        for (int ww = 0; ww < 16; ww++) {
            u64 x0 = s_ws[ww], x1 = s_ws[16 + ww];
            s_ws[ww] = a0; s_ws[16 + ww] = a1;
            a0 += x0; a1 += x1;
        }
    }
    __syncthreads();
    u64 ex0 = s_ws[w] + i0 - c0;        // exclusive prefix (packed)
    u64 ex1 = s_ws[16 + w] + i1 - c1;

    // Phase 3: per-token keep decision; stage results
    int run[8];
#pragma unroll
    for (int e = 0; e < 4; e++) run[e] = (int)((ex0 >> (e * 16)) & 0xffff);
#pragma unroll
    for (int e = 0; e < 4; e++) run[4 + e] = (int)((ex1 >> (e * 16)) & 0xffff);
#pragma unroll
    for (int j = 0; j < 8; j++) {
        int e = eid[j];
        int pos = run[e]++;
        bool keep = pos < CAP;
        s_w[base + j] = keep ? s_w[base + j] : 0.f;
        s_eid[base + j] = (unsigned char)(e | (keep ? 0x80 : 0));
    }
    __syncthreads();

    // Phase 4: coalesced writes (lanes write consecutive tokens)
    float4* dO = (float4*)(dispatch + (size_t)b * SS * 8);
    float4* cO = (float4*)(combine + (size_t)b * SS * 8);
#pragma unroll
    for (int k = 0; k < 8; k++) {
        int tok = k * 512 + t;
        int ec = s_eid[tok];
        int e = ec & 7;
        float keep = (ec & 0x80) ? 1.f : 0.f;
        float cw = s_w[tok];
        float4 d0 = make_float4(e == 0 ? keep : 0.f, e == 1 ? keep : 0.f,
                                e == 2 ? keep : 0.f, e == 3 ? keep : 0.f);
        float4 d1 = make_float4(e == 4 ? keep : 0.f, e == 5 ? keep : 0.f,
                                e == 6 ? keep : 0.f, e == 7 ? keep : 0.f);
        float4 c0v = make_float4(e == 0 ? cw : 0.f, e == 1 ? cw : 0.f,
                                 e == 2 ? cw : 0.f, e == 3 ? cw : 0.f);
        float4 c1v = make_float4(e == 4 ? cw : 0.f, e == 5 ? cw : 0.f,
                                 e == 6 ? cw : 0.f, e == 7 ? cw : 0.f);
        dO[tok * 2] = d0;
        dO[tok * 2 + 1] = d1;
        cO[tok * 2] = c0v;
        cO[tok * 2 + 1] = c1v;
    }
}

// ---------------------------------------------------------------------------
// Kernel 3: deterministic final loss reduction (unused slots are zero)
// ---------------------------------------------------------------------------
__global__ __launch_bounds__(256) void loss_kernel(float* __restrict__ out) {
    __shared__ float rA[256], rB[256];
    int t = threadIdx.x;
    rA[t] = g_part[t * 2] + g_part[(t + 256) * 2];
    rB[t] = g_part[t * 2 + 1] + g_part[(t + 256) * 2 + 1];
    __syncthreads();
    for (int off = 128; off; off >>= 1) {
        if (t < off) { rA[t] += rA[t + off]; rB[t] += rB[t + off]; }
        __syncthreads();
    }
    if (t == 0) {
        out[3 * (size_t)DD + 0] = rA[0] * ((float)EE / (float)NTOK);  // aux_loss
        out[3 * (size_t)DD + 1] = rB[0] / (float)NTOK;                // z_loss
    }
}

extern "C" void kernel_launch(void* const* d_in, const int* in_sizes, int n_in,
                              void* d_out, int out_size) {
    (void)in_sizes; (void)n_in; (void)out_size;
    const float* hid = (const float*)d_in[0];
    const float* W = (const float*)d_in[1];
    float* out = (float*)d_out;

    float* dispatch = out;
    float* combine = out + (size_t)DD;
    float* probs = out + 2 * (size_t)DD;

    cudaFuncSetAttribute(router_kernel, cudaFuncAttributeMaxDynamicSharedMemorySize, 65536);

    router_kernel<<<NBLK, 256, 65536>>>(hid, W, probs);
    dispatch_kernel<<<8, 512>>>(probs, dispatch, combine);
    loss_kernel<<<1, 256>>>(out);
}

// round 14
// speedup vs baseline: 2.9599x; 1.4912x over previous
#include <cuda_runtime.h>

#define SS 4096
#define HH 2048
#define EE 8
#define CAP 512
#define NTOK 32768
#define DD (NTOK*EE)          /* 262144 */
#define K1_GRID 256           /* 256 blocks x 32 quads = 8192 quads = NTOK/4 */

typedef unsigned long long u64;

__device__ float g_part[1024];          // per-K1-block loss partials (512 used)
__device__ unsigned char g_eid[NTOK];   // argmax expert per token
__device__ float g_w[NTOK];             // max prob per token
__device__ int g_cnt[64 * 8];           // [row*8+chunk][expert] counts

__device__ __forceinline__ void ffma2(u64 &acc, u64 a, u64 b) {
    asm("fma.rn.f32x2 %0, %1, %2, %0;" : "+l"(acc) : "l"(a), "l"(b));
}
__device__ __forceinline__ u64 packf2(float a, float b) {
    return (u64)__float_as_uint(a) | ((u64)__float_as_uint(b) << 32);
}
__device__ __forceinline__ float f_lo(u64 v) { return __uint_as_float((unsigned)v); }
__device__ __forceinline__ float f_hi(u64 v) { return __uint_as_float((unsigned)(v >> 32)); }

__device__ __forceinline__ void token_epilogue(const float* lg, float* __restrict__ probs_out,
                                               long tok, float& aux, float& zz) {
    float m = lg[0];
#pragma unroll
    for (int e = 1; e < 8; e++) m = fmaxf(m, lg[e]);
    float p[8];
    float s = 0.f;
#pragma unroll
    for (int e = 0; e < 8; e++) { p[e] = __expf(lg[e] - m); s += p[e]; }
    float inv = 1.f / s;
    float psq = 0.f;
#pragma unroll
    for (int e = 0; e < 8; e++) { p[e] *= inv; psq += p[e] * p[e]; }
    float4* o = (float4*)(probs_out + (size_t)tok * 8);
    o[0] = make_float4(p[0], p[1], p[2], p[3]);
    o[1] = make_float4(p[4], p[5], p[6], p[7]);
    float lse = m + __logf(s);
    aux += psq;
    zz += lse * lse;
}

// ---------------------------------------------------------------------------
// Kernel 1: logits GEMM + softmax + probs + loss partials.
// grid 256, block 256. Thread = (quad of 4 tokens) x (256-wide K segment).
// W amortized over 4 tokens per LDS; distance-1 prefetch on 4 token streams.
// ---------------------------------------------------------------------------
__global__ __launch_bounds__(256, 2) void router_kernel(const float* __restrict__ hid,
                                                        const float* __restrict__ W,
                                                        float* __restrict__ probs_out) {
    extern __shared__ ulonglong2 swp[];  // [e*512 + q]: W[4q..4q+3][e] as 2 f32x2 (64KB)

    int tid = threadIdx.x;
    for (int idx = tid; idx < 4096; idx += 256) {
        int e = idx >> 9;
        int q = idx & 511;
        int h = q * 4;
        ulonglong2 v;
        v.x = packf2(W[(h + 0) * 8 + e], W[(h + 1) * 8 + e]);
        v.y = packf2(W[(h + 2) * 8 + e], W[(h + 3) * 8 + e]);
        swp[idx] = v;
    }
    __syncthreads();

    int kseg = tid & 7;
    int slot = tid >> 3;   // 0..31
    int wid  = tid >> 5;
    long quad = (long)blockIdx.x * 32 + slot;
    long tok0 = quad * 4;

    const ulonglong2* p0 = (const ulonglong2*)(hid + (size_t)tok0 * HH + 4 * kseg);
    const ulonglong2* p1 = p0 + 512;   // +HH floats
    const ulonglong2* p2 = p0 + 1024;
    const ulonglong2* p3 = p0 + 1536;

    u64 acc0[8] = {0,0,0,0,0,0,0,0};
    u64 acc1[8] = {0,0,0,0,0,0,0,0};
    u64 acc2[8] = {0,0,0,0,0,0,0,0};
    u64 acc3[8] = {0,0,0,0,0,0,0,0};

    ulonglong2 c0 = p0[0], c1 = p1[0], c2 = p2[0], c3 = p3[0];

    for (int i = 0; i < 63; i++) {
        ulonglong2 n0 = p0[(i + 1) * 8];   // prefetch next BEFORE consuming cur
        ulonglong2 n1 = p1[(i + 1) * 8];
        ulonglong2 n2 = p2[(i + 1) * 8];
        ulonglong2 n3 = p3[(i + 1) * 8];
        const ulonglong2* ws = &swp[kseg + 8 * i];
#pragma unroll
        for (int e = 0; e < 8; e++) {
            ulonglong2 w = ws[e * 512];
            ffma2(acc0[e], c0.x, w.x);  ffma2(acc0[e], c0.y, w.y);
            ffma2(acc1[e], c1.x, w.x);  ffma2(acc1[e], c1.y, w.y);
            ffma2(acc2[e], c2.x, w.x);  ffma2(acc2[e], c2.y, w.y);
            ffma2(acc3[e], c3.x, w.x);  ffma2(acc3[e], c3.y, w.y);
        }
        c0 = n0; c1 = n1; c2 = n2; c3 = n3;
    }
    {   // tail i = 63
        const ulonglong2* ws = &swp[kseg + 8 * 63];
#pragma unroll
        for (int e = 0; e < 8; e++) {
            ulonglong2 w = ws[e * 512];
            ffma2(acc0[e], c0.x, w.x);  ffma2(acc0[e], c0.y, w.y);
            ffma2(acc1[e], c1.x, w.x);  ffma2(acc1[e], c1.y, w.y);
            ffma2(acc2[e], c2.x, w.x);  ffma2(acc2[e], c2.y, w.y);
            ffma2(acc3[e], c3.x, w.x);  ffma2(acc3[e], c3.y, w.y);
        }
    }

    float lg0[8], lg1[8], lg2[8], lg3[8];
#pragma unroll
    for (int e = 0; e < 8; e++) {
        lg0[e] = f_lo(acc0[e]) + f_hi(acc0[e]);
        lg1[e] = f_lo(acc1[e]) + f_hi(acc1[e]);
        lg2[e] = f_lo(acc2[e]) + f_hi(acc2[e]);
        lg3[e] = f_lo(acc3[e]) + f_hi(acc3[e]);
    }
#pragma unroll
    for (int off = 4; off; off >>= 1) {
#pragma unroll
        for (int e = 0; e < 8; e++) {
            lg0[e] += __shfl_down_sync(0xffffffffu, lg0[e], off, 8);
            lg1[e] += __shfl_down_sync(0xffffffffu, lg1[e], off, 8);
            lg2[e] += __shfl_down_sync(0xffffffffu, lg2[e], off, 8);
            lg3[e] += __shfl_down_sync(0xffffffffu, lg3[e], off, 8);
        }
    }

    float auxAcc = 0.f, zAcc = 0.f;
    if (kseg == 0) {
        token_epilogue(lg0, probs_out, tok0 + 0, auxAcc, zAcc);
        token_epilogue(lg1, probs_out, tok0 + 1, auxAcc, zAcc);
        token_epilogue(lg2, probs_out, tok0 + 2, auxAcc, zAcc);
        token_epilogue(lg3, probs_out, tok0 + 3, auxAcc, zAcc);
    }

#pragma unroll
    for (int off = 16; off; off >>= 1) {
        auxAcc += __shfl_down_sync(0xffffffffu, auxAcc, off);
        zAcc   += __shfl_down_sync(0xffffffffu, zAcc, off);
    }
    __shared__ float sA[8], sB[8];
    if ((tid & 31) == 0) { sA[wid] = auxAcc; sB[wid] = zAcc; }
    __syncthreads();
    if (tid == 0) {
        float a = 0.f, z = 0.f;
#pragma unroll
        for (int w = 0; w < 8; w++) { a += sA[w]; z += sB[w]; }
        g_part[blockIdx.x * 2 + 0] = a;
        g_part[blockIdx.x * 2 + 1] = z;
    }
}

// ---------------------------------------------------------------------------
// Kernel 2a: argmax + per-chunk expert counts (grid 64 = 8 rows x 8 chunks),
// plus fused loss reduction in block 0.
// ---------------------------------------------------------------------------
__global__ __launch_bounds__(512) void argmax_kernel(const float* __restrict__ probs,
                                                     float* __restrict__ out) {
    int b = blockIdx.x;
    int row = b >> 3, chunk = b & 7;
    int t = threadIdx.x;
    __shared__ int scnt[8];
    if (t < 8) scnt[t] = 0;
    __syncthreads();

    int tokr = chunk * 512 + t;
    int gi = row * SS + tokr;
    const float4* pr = (const float4*)(probs + (size_t)gi * 8);
    float4 lo = pr[0];
    float4 hi = pr[1];
    float v[8] = {lo.x, lo.y, lo.z, lo.w, hi.x, hi.y, hi.z, hi.w};
    float m = v[0];
    int mi = 0;
#pragma unroll
    for (int e = 1; e < 8; e++)
        if (v[e] > m) { m = v[e]; mi = e; }
    g_eid[gi] = (unsigned char)mi;
    g_w[gi] = m;
    atomicAdd(&scnt[mi], 1);
    __syncthreads();
    if (t < 8) g_cnt[b * 8 + t] = scnt[t];

    // fused loss reduction (K1 grid = 256 -> 512 partial floats)
    if (b == 0) {
        __shared__ float rA[256], rB[256];
        if (t < 256) { rA[t] = g_part[t * 2]; rB[t] = g_part[t * 2 + 1]; }
        __syncthreads();
        for (int off = 128; off; off >>= 1) {
            if (t < off) { rA[t] += rA[t + off]; rB[t] += rB[t + off]; }
            __syncthreads();
        }
        if (t == 0) {
            out[3 * (size_t)DD + 0] = rA[0] * ((float)EE / (float)NTOK);  // aux_loss
            out[3 * (size_t)DD + 1] = rB[0] / (float)NTOK;                // z_loss
        }
    }
}

// ---------------------------------------------------------------------------
// Kernel 2b: capacity positions + emit dispatch/combine (grid 64).
// pos(token) = sum of counts in earlier chunks (same row) + in-block prefix.
// ---------------------------------------------------------------------------
__global__ __launch_bounds__(512) void dispatch_kernel(float* __restrict__ dispatch,
                                                       float* __restrict__ combine) {
    int b = blockIdx.x;
    int row = b >> 3, chunk = b & 7;
    int t = threadIdx.x;
    int lane = t & 31;
    int w = t >> 5;  // 0..15
    __shared__ u64 s_ws[32];
    __shared__ int base8[8];

    int tokr = chunk * 512 + t;
    int gi = row * SS + tokr;
    int e = g_eid[gi];
    float wv = g_w[gi];

    u64 cc0 = (e < 4) ? (1ULL << (e * 16)) : 0ULL;
    u64 cc1 = (e >= 4) ? (1ULL << ((e - 4) * 16)) : 0ULL;
    u64 i0 = cc0, i1 = cc1;
#pragma unroll
    for (int off = 1; off < 32; off <<= 1) {
        u64 n0 = __shfl_up_sync(0xffffffffu, i0, off);
        u64 n1 = __shfl_up_sync(0xffffffffu, i1, off);
        if (lane >= off) { i0 += n0; i1 += n1; }
    }
    if (lane == 31) { s_ws[w] = i0; s_ws[16 + w] = i1; }
    if (t < 8) {
        int s = 0;
        for (int c = 0; c < chunk; c++) s += g_cnt[(row * 8 + c) * 8 + t];
        base8[t] = s;
    }
    __syncthreads();
    if (t == 0) {
        u64 a0 = 0, a1 = 0;
        for (int ww = 0; ww < 16; ww++) {
            u64 x0 = s_ws[ww], x1 = s_ws[16 + ww];
            s_ws[ww] = a0; s_ws[16 + ww] = a1;
            a0 += x0; a1 += x1;
        }
    }
    __syncthreads();
    u64 ex0 = s_ws[w] + i0 - cc0;
    u64 ex1 = s_ws[16 + w] + i1 - cc1;
    int pref = (e < 4) ? (int)((ex0 >> (e * 16)) & 0xffff)
                       : (int)((ex1 >> ((e - 4) * 16)) & 0xffff);
    int pos = base8[e] + pref;
    float keep = (pos < CAP) ? 1.f : 0.f;
    float cw = keep * wv;

    float4* dO = (float4*)(dispatch + (size_t)gi * 8);
    float4* cO = (float4*)(combine + (size_t)gi * 8);
    dO[0] = make_float4(e == 0 ? keep : 0.f, e == 1 ? keep : 0.f,
                        e == 2 ? keep : 0.f, e == 3 ? keep : 0.f);
    dO[1] = make_float4(e == 4 ? keep : 0.f, e == 5 ? keep : 0.f,
                        e == 6 ? keep : 0.f, e == 7 ? keep : 0.f);
    cO[0] = make_float4(e == 0 ? cw : 0.f, e == 1 ? cw : 0.f,
                        e == 2 ? cw : 0.f, e == 3 ? cw : 0.f);
    cO[1] = make_float4(e == 4 ? cw : 0.f, e == 5 ? cw : 0.f,
                        e == 6 ? cw : 0.f, e == 7 ? cw : 0.f);
}

extern "C" void kernel_launch(void* const* d_in, const int* in_sizes, int n_in,
                              void* d_out, int out_size) {
    (void)in_sizes; (void)n_in; (void)out_size;
    const float* hid = (const float*)d_in[0];
    const float* W = (const float*)d_in[1];
    float* out = (float*)d_out;

    float* dispatch = out;
    float* combine = out + (size_t)DD;
    float* probs = out + 2 * (size_t)DD;

    cudaFuncSetAttribute(router_kernel, cudaFuncAttributeMaxDynamicSharedMemorySize, 65536);

    router_kernel<<<K1_GRID, 256, 65536>>>(hid, W, probs);
    argmax_kernel<<<64, 512>>>(probs, out);
    dispatch_kernel<<<64, 512>>>(dispatch, combine);
}